// round 1
// baseline (speedup 1.0000x reference)
#include <cuda_runtime.h>

// Fixed problem shapes (QGenBelief reference)
#define B   64
#define Q   16
#define O   20
#define D   256
#define T   4096
// float4 lanes per D-row
#define D4  (D / 4)   // 64

// Scratch: belief table [B, Q, D] f32 = 1 MB (device global; no allocation allowed)
__device__ float g_belief[B * Q * D];

// ---------------------------------------------------------------------------
// Kernel 1: belief[b,q,:] = tanh( softmax(logits[b,q,:]) @ emb[cat[b,:], :] )
// One block per (b,q) row; 256 threads (one per d).
// ---------------------------------------------------------------------------
__global__ __launch_bounds__(D) void belief_kernel(
    const float* __restrict__ logits,      // [B,Q,O]
    const float* __restrict__ emb,         // [NUM_CAT, D]
    const int*   __restrict__ cats)        // [B,O]
{
    const int bq = blockIdx.x;             // 0 .. B*Q-1
    const int b  = bq / Q;

    __shared__ float s_p[O];
    __shared__ int   s_cat[O];

    const int tid = threadIdx.x;
    if (tid < O) {
        s_p[tid]   = logits[bq * O + tid];
        s_cat[tid] = cats[b * O + tid];
    }
    __syncthreads();

    // Softmax over 20 elements — serial on thread 0, trivially cheap.
    if (tid == 0) {
        float m = s_p[0];
        #pragma unroll
        for (int o = 1; o < O; ++o) m = fmaxf(m, s_p[o]);
        float s = 0.f;
        #pragma unroll
        for (int o = 0; o < O; ++o) { float e = __expf(s_p[o] - m); s_p[o] = e; s += e; }
        float inv = 1.f / s;
        #pragma unroll
        for (int o = 0; o < O; ++o) s_p[o] *= inv;
    }
    __syncthreads();

    // Each thread owns one d column. Coalesced emb loads per warp.
    float acc = 0.f;
    #pragma unroll
    for (int o = 0; o < O; ++o) {
        acc = fmaf(s_p[o], emb[s_cat[o] * D + tid], acc);
    }
    g_belief[bq * D + tid] = tanhf(acc);
}

// ---------------------------------------------------------------------------
// Kernel 2: scatter belief rows to [B, T, D] output per question-ownership of
// each token t; zero where invalid.
// Block = 256 threads = 4 t-rows x 64 float4 lanes. Grid = (T/4, B).
// ---------------------------------------------------------------------------
__global__ __launch_bounds__(256) void scatter_kernel(
    const int*  __restrict__ cum,     // [B,Q]
    const int*  __restrict__ nq,      // [B]
    float4*     __restrict__ out)     // [B,T,D] viewed as float4
{
    const int b  = blockIdx.y;
    const int t0 = blockIdx.x * 4;

    __shared__ int s_bnd[Q - 1];
    __shared__ int s_nq;

    const int tid = threadIdx.x;
    if (tid < Q - 1) s_bnd[tid] = cum[b * Q + 1 + tid] - 1;
    if (tid == 0)    s_nq = nq[b];
    __syncthreads();

    const int r  = tid >> 6;        // 0..3 : which t-row in this block
    const int d4 = tid & 63;        // float4 lane
    const int t  = t0 + r;
    const int nqb = s_nq;

    // qi = number of active boundaries <= t  (boundary j active iff j <= nqb-1)
    int qi = 0;
    #pragma unroll
    for (int j = 1; j < Q; ++j) {
        if (j <= nqb - 1 && t >= s_bnd[j - 1]) qi++;
    }

    const bool valid = qi < (nqb - 1);

    float4 v;
    if (valid) {
        v = reinterpret_cast<const float4*>(g_belief)[(b * Q + qi) * D4 + d4];
    } else {
        v = make_float4(0.f, 0.f, 0.f, 0.f);
    }

    out[(size_t)(b * T + t) * D4 + d4] = v;
}

// ---------------------------------------------------------------------------
// Launch contract
// Inputs (metadata order): object_logits f32 [B,Q,O], emb_table f32 [NUM_CAT,D],
// object_categories i32 [B,O], cumulative_lengths i32 [B,Q], num_questions i32 [B],
// max_dln (scalar, unused — T hardcoded). Output: f32 [B,T,D].
// ---------------------------------------------------------------------------
extern "C" void kernel_launch(void* const* d_in, const int* in_sizes, int n_in,
                              void* d_out, int out_size)
{
    const float* logits = (const float*)d_in[0];
    const float* emb    = (const float*)d_in[1];
    const int*   cats   = (const int*)d_in[2];
    const int*   cum    = (const int*)d_in[3];
    const int*   nq     = (const int*)d_in[4];

    belief_kernel<<<B * Q, D>>>(logits, emb, cats);

    dim3 grid(T / 4, B);
    scatter_kernel<<<grid, 256>>>(cum, nq, (float4*)d_out);
}

// round 2
// speedup vs baseline: 1.4178x; 1.4178x over previous
#include <cuda_runtime.h>

// Fixed problem shapes (QGenBelief reference)
#define B   64
#define Q   16
#define O   20
#define D   256
#define T   4096
#define D4  (D / 4)          // 64 float4 lanes per row
#define RPB 32               // t-rows per scatter block
#define RPT 8                // t-rows per thread (RPB / 4 groups)

// Scratch: belief table [B, Q, D] f32 = 1 MB
__device__ float g_belief[B * Q * D];

__device__ __forceinline__ float fast_tanh(float x) {
    float y;
    asm("tanh.approx.f32 %0, %1;" : "=f"(y) : "f"(x));
    return y;
}

// ---------------------------------------------------------------------------
// Kernel 1: belief[b,q,:] = tanh( softmax(logits[b,q,:]) @ emb[cat[b,:], :] )
// One block per b; emb rows staged once in shared; loop over q.
// ---------------------------------------------------------------------------
__global__ __launch_bounds__(D) void belief_kernel(
    const float* __restrict__ logits,      // [B,Q,O]
    const float* __restrict__ emb,         // [NUM_CAT, D]
    const int*   __restrict__ cats)        // [B,O]
{
    const int b   = blockIdx.x;
    const int tid = threadIdx.x;

    __shared__ float s_emb[O * D];         // 20 KB
    __shared__ float s_p[Q * O];           // probs
    __shared__ int   s_cat[O];

    if (tid < O) s_cat[tid] = cats[b * O + tid];
    __syncthreads();

    // Stage embedding rows for this batch's 20 categories.
    #pragma unroll
    for (int o = 0; o < O; ++o)
        s_emb[o * D + tid] = emb[s_cat[o] * D + tid];

    // Softmax: thread q handles question q (serial over 20 — trivial).
    if (tid < Q) {
        float v[O];
        #pragma unroll
        for (int o = 0; o < O; ++o) v[o] = logits[(b * Q + tid) * O + o];
        float m = v[0];
        #pragma unroll
        for (int o = 1; o < O; ++o) m = fmaxf(m, v[o]);
        float s = 0.f;
        #pragma unroll
        for (int o = 0; o < O; ++o) { v[o] = __expf(v[o] - m); s += v[o]; }
        float inv = 1.f / s;
        #pragma unroll
        for (int o = 0; o < O; ++o) s_p[tid * O + o] = v[o] * inv;
    }
    __syncthreads();

    // Each thread owns column d = tid; loop over the 16 questions.
    #pragma unroll 4
    for (int q = 0; q < Q; ++q) {
        float acc = 0.f;
        #pragma unroll
        for (int o = 0; o < O; ++o)
            acc = fmaf(s_p[q * O + o], s_emb[o * D + tid], acc);
        g_belief[(b * Q + q) * D + tid] = fast_tanh(acc);
    }
}

// ---------------------------------------------------------------------------
// Kernel 2: scatter. Block covers 32 consecutive t-rows of one batch.
// qi per row computed once into shared; each thread stores 8 rows at one
// float4 lane, reloading the belief vector only on qi change.
// ---------------------------------------------------------------------------
__global__ __launch_bounds__(256) void scatter_kernel(
    const int*  __restrict__ cum,     // [B,Q]
    const int*  __restrict__ nq,      // [B]
    float4*     __restrict__ out)     // [B,T,D] as float4
{
    const int b  = blockIdx.y;
    const int t0 = blockIdx.x * RPB;
    const int tid = threadIdx.x;

    __shared__ int s_bnd[Q - 1];
    __shared__ int s_nq;
    __shared__ int s_qi[RPB];

    if (tid < Q - 1) s_bnd[tid] = cum[b * Q + 1 + tid] - 1;
    if (tid == Q - 1) s_nq = nq[b];
    __syncthreads();

    if (tid < RPB) {
        const int t   = t0 + tid;
        const int nqb = s_nq;
        int qi = 0;
        #pragma unroll
        for (int j = 1; j < Q; ++j)
            if (j <= nqb - 1 && t >= s_bnd[j - 1]) qi++;
        s_qi[tid] = (qi < nqb - 1) ? qi : -1;   // -1 => write zeros
    }
    __syncthreads();

    const int g  = tid >> 6;          // row-group 0..3
    const int d4 = tid & 63;          // float4 lane

    const float4* bel = reinterpret_cast<const float4*>(g_belief)
                        + (b * Q) * D4 + d4;
    float4* o = out + ((size_t)b * T + t0 + g * RPT) * D4 + d4;

    int   prev = -2;
    float4 v = make_float4(0.f, 0.f, 0.f, 0.f);

    #pragma unroll
    for (int i = 0; i < RPT; ++i) {
        const int qi = s_qi[g * RPT + i];     // broadcast within warp
        if (qi != prev) {
            prev = qi;
            v = (qi >= 0) ? bel[qi * D4] : make_float4(0.f, 0.f, 0.f, 0.f);
        }
        o[i * D4] = v;
    }
}

// ---------------------------------------------------------------------------
extern "C" void kernel_launch(void* const* d_in, const int* in_sizes, int n_in,
                              void* d_out, int out_size)
{
    const float* logits = (const float*)d_in[0];
    const float* emb    = (const float*)d_in[1];
    const int*   cats   = (const int*)d_in[2];
    const int*   cum    = (const int*)d_in[3];
    const int*   nq     = (const int*)d_in[4];

    belief_kernel<<<B, D>>>(logits, emb, cats);

    dim3 grid(T / RPB, B);
    scatter_kernel<<<grid, 256>>>(cum, nq, (float4*)d_out);
}

// round 4
// speedup vs baseline: 1.5442x; 1.0892x over previous
#include <cuda_runtime.h>

// Fixed problem shapes (QGenBelief reference)
#define B   64
#define Q   16
#define O   20
#define D   256
#define T   4096
#define D4  (D / 4)          // 64 float4 lanes per row
#define RPB 64               // t-rows per scatter block
#define RPT 16               // t-rows per thread (RPB / 4 row-groups)

// Scratch: belief table [B, Q, D] f32 = 1 MB
__device__ float g_belief[B * Q * D];

__device__ __forceinline__ float fast_tanh(float x) {
    float y;
    asm("tanh.approx.f32 %0, %1;" : "=f"(y) : "f"(x));
    return y;
}

// ---------------------------------------------------------------------------
// Kernel 1: belief[b,q,:] = tanh( softmax(logits[b,q,:]) @ emb[cat[b,:], :] )
// One block per (b,q); 256 threads (one per d). Emb table is L2-resident.
// ---------------------------------------------------------------------------
__global__ __launch_bounds__(D) void belief_kernel(
    const float* __restrict__ logits,      // [B,Q,O]
    const float* __restrict__ emb,         // [NUM_CAT, D]
    const int*   __restrict__ cats)        // [B,O]
{
    const int bq = blockIdx.x;             // 0 .. B*Q-1
    const int b  = bq / Q;
    const int tid = threadIdx.x;

    __shared__ float s_p[O];
    __shared__ int   s_cat[O];

    if (tid < O) {
        s_p[tid]   = logits[bq * O + tid];
        s_cat[tid] = cats[b * O + tid];
    }
    __syncthreads();

    if (tid == 0) {
        float m = s_p[0];
        #pragma unroll
        for (int o = 1; o < O; ++o) m = fmaxf(m, s_p[o]);
        float s = 0.f;
        #pragma unroll
        for (int o = 0; o < O; ++o) { float e = __expf(s_p[o] - m); s_p[o] = e; s += e; }
        float inv = 1.f / s;
        #pragma unroll
        for (int o = 0; o < O; ++o) s_p[o] *= inv;
    }
    __syncthreads();

    float acc = 0.f;
    #pragma unroll
    for (int o = 0; o < O; ++o)
        acc = fmaf(s_p[o], emb[s_cat[o] * D + tid], acc);

    g_belief[bq * D + tid] = fast_tanh(acc);
}

// ---------------------------------------------------------------------------
// Kernel 2: scatter. Block covers 64 consecutive t-rows of one batch.
// qi per row computed once into shared; each thread streams 16 rows at one
// float4 lane, reloading the belief vector only on qi change.
// ---------------------------------------------------------------------------
__global__ __launch_bounds__(256) void scatter_kernel(
    const int*  __restrict__ cum,     // [B,Q]
    const int*  __restrict__ nq,      // [B]
    float4*     __restrict__ out)     // [B,T,D] as float4
{
    const int b   = blockIdx.y;
    const int t0  = blockIdx.x * RPB;
    const int tid = threadIdx.x;

    __shared__ int s_bnd[Q - 1];
    __shared__ int s_nq;
    __shared__ int s_qi[RPB];

    if (tid < Q - 1) s_bnd[tid] = cum[b * Q + 1 + tid] - 1;
    if (tid == Q - 1) s_nq = nq[b];
    __syncthreads();

    if (tid < RPB) {
        const int t   = t0 + tid;
        const int nqb = s_nq;
        int qi = 0;
        #pragma unroll
        for (int j = 1; j < Q; ++j)
            if (j <= nqb - 1 && t >= s_bnd[j - 1]) qi++;
        s_qi[tid] = (qi < nqb - 1) ? qi : -1;   // -1 => zeros
    }
    __syncthreads();

    const int g  = tid >> 6;          // row-group 0..3
    const int d4 = tid & 63;          // float4 lane

    const float4* bel = reinterpret_cast<const float4*>(g_belief)
                        + (b * Q) * D4 + d4;
    float4* o = out + ((size_t)b * T + t0 + g * RPT) * D4 + d4;

    int    prev = -2;
    float4 v = make_float4(0.f, 0.f, 0.f, 0.f);

    #pragma unroll
    for (int i = 0; i < RPT; ++i) {
        const int qi = s_qi[g * RPT + i];     // warp-uniform broadcast
        if (qi != prev) {
            prev = qi;
            v = (qi >= 0) ? bel[qi * D4] : make_float4(0.f, 0.f, 0.f, 0.f);
        }
        __stcs(o + i * D4, v);                // streaming store, evict-first
    }
}

// ---------------------------------------------------------------------------
extern "C" void kernel_launch(void* const* d_in, const int* in_sizes, int n_in,
                              void* d_out, int out_size)
{
    const float* logits = (const float*)d_in[0];
    const float* emb    = (const float*)d_in[1];
    const int*   cats   = (const int*)d_in[2];
    const int*   cum    = (const int*)d_in[3];
    const int*   nq     = (const int*)d_in[4];

    belief_kernel<<<B * Q, D>>>(logits, emb, cats);

    dim3 grid(T / RPB, B);
    scatter_kernel<<<grid, 256>>>(cum, nq, (float4*)d_out);
}